// round 15
// baseline (speedup 1.0000x reference)
#include <cuda_runtime.h>
#include <math.h>
#include <stdint.h>

#define B_ 4
#define C_ 128
#define N_ 512
#define T_ 16
#define H_ 4
#define DK_ 32
#define RSCALE 0.17677669529663687f   /* 1/sqrt(32) */
#define QSCALE 0.2550267247806026f    /* RSCALE * log2(e) */
#define L2E    1.4426950408889634f

// ---------------- PTX helpers ----------------
__device__ __forceinline__ void mma_tf32(float* d, const uint32_t* a, uint32_t b0, uint32_t b1) {
    asm("mma.sync.aligned.m16n8k8.row.col.f32.tf32.tf32.f32 "
        "{%0,%1,%2,%3}, {%4,%5,%6,%7}, {%8,%9}, {%0,%1,%2,%3};"
        : "+f"(d[0]), "+f"(d[1]), "+f"(d[2]), "+f"(d[3])
        : "r"(a[0]), "r"(a[1]), "r"(a[2]), "r"(a[3]), "r"(b0), "r"(b1));
}

__device__ __forceinline__ void mma_bf16(float* d, const uint32_t* a, uint32_t b0, uint32_t b1) {
    asm("mma.sync.aligned.m16n8k16.row.col.f32.bf16.bf16.f32 "
        "{%0,%1,%2,%3}, {%4,%5,%6,%7}, {%8,%9}, {%0,%1,%2,%3};"
        : "+f"(d[0]), "+f"(d[1]), "+f"(d[2]), "+f"(d[3])
        : "r"(a[0]), "r"(a[1]), "r"(a[2]), "r"(a[3]), "r"(b0), "r"(b1));
}

// round-to-nearest fp32 -> tf32 (fp32 bits, low 13 mantissa bits zero)
__device__ __forceinline__ uint32_t f2tf(float f) {
    uint32_t r;
    asm("cvt.rna.tf32.f32 %0, %1;" : "=r"(r) : "f"(f));
    return r;
}

// pack two fp32 -> bf16x2 {lo, hi}
__device__ __forceinline__ uint32_t bf2(float hi, float lo) {
    uint32_t r;
    asm("cvt.rn.bf16x2.f32 %0, %1, %2;" : "=r"(r) : "f"(hi), "f"(lo));
    return r;
}

__device__ __forceinline__ float ex2f(float x) {
    float r;
    asm("ex2.approx.f32 %0, %1;" : "=f"(r) : "f"(x));
    return r;
}

__device__ __forceinline__ void cp16(void* dst, const void* src) {
    uint32_t s = (uint32_t)__cvta_generic_to_shared(dst);
    asm volatile("cp.async.cg.shared.global [%0], [%1], 16;" :: "r"(s), "l"(src));
}
__device__ __forceinline__ void cp_commit() {
    asm volatile("cp.async.commit_group;" ::: "memory");
}
template <int NN> __device__ __forceinline__ void cp_wait() {
    asm volatile("cp.async.wait_group %0;" :: "n"(NN) : "memory");
}

// ---------------- scratch ----------------
__device__ float g_x2[B_*C_*T_*N_];            // x2[b][c][t][n], PRE-ROUNDED to tf32 grid
__device__ uint32_t g_x2b[B_*T_*64*512];       // bf16x2: [b][t][c2][n]
__device__ uint32_t g_Wqp[128*64];             // bf16x2 packed Wq[o][c2]
__device__ uint32_t g_Wkp[128*64];
__device__ uint32_t g_Qp[B_*T_*H_*16*512];     // bf16x2 QSCALE*Q pairs along d
__device__ uint32_t g_Kp[B_*T_*H_*16*512];
__device__ float g_acc[B_*N_*N_];              // sum over (t,h) of softmax probs
__device__ float g_stS[N_*N_];
__device__ float g_fused[B_*N_*N_];            // E = exp(logits), tf32-rounded, unnormalized
__device__ float g_S[B_*N_];                   // row sums of rounded E

// ---------------- small helpers ----------------
__device__ __forceinline__ float blk_reduce_max(float v, float* red, int tid) {
    #pragma unroll
    for (int off = 16; off > 0; off >>= 1)
        v = fmaxf(v, __shfl_xor_sync(0xffffffffu, v, off));
    if ((tid & 31) == 0) red[tid >> 5] = v;
    __syncthreads();
    if (tid == 0) {
        float m = red[0];
        #pragma unroll
        for (int k = 1; k < 8; k++) m = fmaxf(m, red[k]);
        red[0] = m;
    }
    __syncthreads();
    float r = red[0];
    __syncthreads();
    return r;
}

__device__ __forceinline__ float blk_reduce_sum(float v, float* red, int tid) {
    #pragma unroll
    for (int off = 16; off > 0; off >>= 1)
        v += __shfl_xor_sync(0xffffffffu, v, off);
    if ((tid & 31) == 0) red[tid >> 5] = v;
    __syncthreads();
    if (tid == 0) {
        float m = red[0];
        #pragma unroll
        for (int k = 1; k < 8; k++) m += red[k];
        red[0] = m;
    }
    __syncthreads();
    float r = red[0];
    __syncthreads();
    return r;
}

// ---------------- dummy (keeps score_kernel at ncu's capture slot) ----------------
__global__ void dummy_kernel() {}

// ---------------- prep ----------------
__global__ __launch_bounds__(256) void prep_kernel(const float* __restrict__ x,
                                                   const float* __restrict__ st,
                                                   const float* __restrict__ Wq,
                                                   const float* __restrict__ Wk) {
    extern __shared__ float dsh[];
    __shared__ float red[8];
    int bk = blockIdx.x, tid = threadIdx.x;
    if (bk < 256) {
        float* s0 = dsh;
        float* s1 = dsh + 8208;
        int bc0 = 2 * bk, bc1 = bc0 + 1;
        const float* src0 = x + (size_t)bc0 * (N_ * T_);
        const float* src1 = x + (size_t)bc1 * (N_ * T_);
        for (int i = tid; i < N_ * T_; i += 256) {
            int n = i >> 4, t = i & 15;
            s0[t * (N_ + 1) + n] = src0[i];
            s1[t * (N_ + 1) + n] = src1[i];
        }
        __syncthreads();
        float* dst0 = g_x2 + (size_t)bc0 * (T_ * N_);
        float* dst1 = g_x2 + (size_t)bc1 * (T_ * N_);
        int b = bc0 >> 7, c2 = (bc0 & 127) >> 1;
        for (int o = tid; o < N_ * T_; o += 256) {
            int t = o >> 9, n = o & 511;
            float v0 = s0[t * (N_ + 1) + n];
            float v1 = s1[t * (N_ + 1) + n];
            dst0[o] = __uint_as_float(f2tf(v0));
            dst1[o] = __uint_as_float(f2tf(v1));
            g_x2b[((size_t)(b * T_ + t) * 64 + c2) * 512 + n] = bf2(v1, v0);
        }
    } else if (bk < 768) {
        int i = bk - 256;
        float v0 = st[(size_t)i * N_ + tid];
        float v1 = st[(size_t)i * N_ + tid + 256];
        float m = blk_reduce_max(fmaxf(v0, v1), red, tid);
        float e0 = __expf(v0 - m), e1 = __expf(v1 - m);
        float ss = blk_reduce_sum(e0 + e1, red, tid);
        float inv = __fdividef(1.f, ss);
        g_stS[(size_t)i * N_ + tid] = e0 * inv;
        g_stS[(size_t)i * N_ + tid + 256] = e1 * inv;
    } else if (bk < 1024) {
        int zb = bk - 768;
        float4 z = make_float4(0.f, 0.f, 0.f, 0.f);
        float4* a4 = reinterpret_cast<float4*>(g_acc);
        #pragma unroll
        for (int k = 0; k < 4; k++)
            a4[(size_t)zb * 1024 + k * 256 + tid] = z;
        if (zb < 2)
            reinterpret_cast<float4*>(g_S)[zb * 256 + tid] = z;
    } else {
        int idx = (bk - 1024) * 1024 + tid * 4;
        #pragma unroll
        for (int u = 0; u < 4; u++) {
            int f = idx + u;
            int o = f >> 6, c2 = f & 63;
            float2 wv = *reinterpret_cast<const float2*>(&Wq[o * 128 + 2 * c2]);
            g_Wqp[f] = bf2(wv.y, wv.x);
            float2 kv = *reinterpret_cast<const float2*>(&Wk[o * 128 + 2 * c2]);
            g_Wkp[f] = bf2(kv.y, kv.x);
        }
    }
}

// ---------------- projection via bf16 m16n8k16 (merged Q+K, pre-packed W) --------
__global__ __launch_bounds__(256, 2) void proj_kernel() {
    extern __shared__ uint32_t shw[];
    uint32_t* Wqp = shw;
    uint32_t* Wkp = shw + 8704;
    uint32_t* Xb0 = shw + 17408;
    uint32_t* Xb1 = shw + 19968;
    int n0 = blockIdx.x * 128;
    int bt = blockIdx.y;
    int b = bt >> 4, t = bt & 15;
    int tid = threadIdx.x, w = tid >> 5, lane = tid & 31;
    int lq = lane >> 2, lr = lane & 3;
    int o_lo = 16 * w + lq, o_hi = o_lo + 8;

    const uint32_t* xsrc = g_x2b + ((size_t)(b * T_ + t) * 64) * 512 + n0;

    #define PROJ_STAGE(X, ch)                                                          \
        {                                                                              \
            _Pragma("unroll")                                                          \
            for (int i = 0; i < 2; i++) {                                              \
                int f = tid + 256 * i;                                                 \
                int c2 = f >> 3, g = f & 7;                                            \
                cp16(&(X)[c2 * 40 + 4 * g], xsrc + (size_t)c2 * 512 + (ch) * 32 + 4 * g); \
            }                                                                          \
        }

    #pragma unroll
    for (int i = 0; i < 8; i++) {
        int f = tid + 256 * i;
        int o = f >> 4, g = f & 15;
        cp16(&Wqp[o * 68 + 4 * g], &g_Wqp[o * 64 + 4 * g]);
        cp16(&Wkp[o * 68 + 4 * g], &g_Wkp[o * 64 + 4 * g]);
    }
    cp_commit();
    PROJ_STAGE(Xb0, 0);
    cp_commit();

    cp_wait<1>();
    __syncthreads();

    uint32_t aq[8][4];
    #pragma unroll
    for (int s = 0; s < 8; s++) {
        aq[s][0] = Wqp[o_lo * 68 + 8 * s + lr];
        aq[s][1] = Wqp[o_hi * 68 + 8 * s + lr];
        aq[s][2] = Wqp[o_lo * 68 + 8 * s + lr + 4];
        aq[s][3] = Wqp[o_hi * 68 + 8 * s + lr + 4];
    }

    int h = w >> 1;
    bool qside = ((lane & 4) == 0);
    int o_loc = (16 * w + lq) & 31;
    int d2 = (qside ? o_loc : (o_loc - 1)) >> 1;
    size_t kb = (((size_t)(b * T_ + t) * H_ + h) * 16) * 512;

    for (int ch = 0; ch < 4; ch++) {
        uint32_t* Xn = (ch & 1) ? Xb0 : Xb1;
        if (ch < 3) {
            PROJ_STAGE(Xn, ch + 1);
            cp_commit();
            cp_wait<1>();
        } else {
            cp_wait<0>();
        }
        __syncthreads();
        const uint32_t* X = (ch & 1) ? Xb1 : Xb0;

        float accq[4][4], acck[4][4];
        #pragma unroll
        for (int j = 0; j < 4; j++)
            #pragma unroll
            for (int k = 0; k < 4; k++) { accq[j][k] = 0.f; acck[j][k] = 0.f; }

        #pragma unroll
        for (int s = 0; s < 8; s++) {
            uint32_t ak[4];
            ak[0] = Wkp[o_lo * 68 + 8 * s + lr];
            ak[1] = Wkp[o_hi * 68 + 8 * s + lr];
            ak[2] = Wkp[o_lo * 68 + 8 * s + lr + 4];
            ak[3] = Wkp[o_hi * 68 + 8 * s + lr + 4];
            #pragma unroll
            for (int j = 0; j < 4; j++) {
                uint32_t b0 = X[(8 * s + lr) * 40 + 8 * j + lq];
                uint32_t b1 = X[(8 * s + lr + 4) * 40 + 8 * j + lq];
                mma_bf16(accq[j], aq[s], b0, b1);
                mma_bf16(acck[j], ak, b0, b1);
            }
        }

        #pragma unroll
        for (int j = 0; j < 4; j++)
            #pragma unroll
            for (int k = 0; k < 4; k++) accq[j][k] *= QSCALE;

        #pragma unroll
        for (int j = 0; j < 4; j++) {
            float q0 = __shfl_xor_sync(0xffffffffu, accq[j][0], 4);
            float q1 = __shfl_xor_sync(0xffffffffu, accq[j][1], 4);
            float q2 = __shfl_xor_sync(0xffffffffu, accq[j][2], 4);
            float q3 = __shfl_xor_sync(0xffffffffu, accq[j][3], 4);
            float k0 = __shfl_xor_sync(0xffffffffu, acck[j][0], 4);
            float k1 = __shfl_xor_sync(0xffffffffu, acck[j][1], 4);
            float k2 = __shfl_xor_sync(0xffffffffu, acck[j][2], 4);
            float k3 = __shfl_xor_sync(0xffffffffu, acck[j][3], 4);
            int n = n0 + ch * 32 + 8 * j + 2 * lr;
            uint2 lo2, hi2;
            uint32_t* dst;
            if (qside) {
                dst = g_Qp;
                lo2.x = bf2(q0, accq[j][0]); lo2.y = bf2(q1, accq[j][1]);
                hi2.x = bf2(q2, accq[j][2]); hi2.y = bf2(q3, accq[j][3]);
            } else {
                dst = g_Kp;
                lo2.x = bf2(acck[j][0], k0); lo2.y = bf2(acck[j][1], k1);
                hi2.x = bf2(acck[j][2], k2); hi2.y = bf2(acck[j][3], k3);
            }
            *reinterpret_cast<uint2*>(&dst[kb + (size_t)d2 * 512 + n]) = lo2;
            *reinterpret_cast<uint2*>(&dst[kb + (size_t)(d2 + 4) * 512 + n]) = hi2;
        }
        __syncthreads();
    }
    #undef PROJ_STAGE
}

// ---------------- scores: 512 threads, pipelined normalization (1 barrier/t) -----
// acc double-buffered by t-parity; probs of t are normalized at t+1 using
// rowsum[t], which is complete by the staging barrier of t+1.
__global__ __launch_bounds__(512) void score_kernel() {
    extern __shared__ uint32_t shw[];
    const int KS_W = 16 * 520;
    const int QS_W = 16 * 40;
    const int BUF_W = KS_W + QS_W;       // 8960
    float* rowsum = reinterpret_cast<float*>(shw + 2 * BUF_W);   // [16][32]
    int nt = blockIdx.x, h = blockIdx.y, b = blockIdx.z;
    int n0 = nt * 32;
    int tid = threadIdx.x, w = tid >> 5, lane = tid & 31;
    int rowgrp = w & 1, colgrp = w >> 1;
    int lq = lane >> 2, lr = lane & 3;
    int r_lo = 16 * rowgrp + lq, r_hi = r_lo + 8;

    rowsum[tid] = 0.f;   // 512 = 16*32 exactly

    float pacc[8][4];
    float abuf[2][8][4];
    #pragma unroll
    for (int j = 0; j < 8; j++)
        #pragma unroll
        for (int k = 0; k < 4; k++) pacc[j][k] = 0.f;

    #define SCORE_STAGE(tt, buf)                                                       \
        {                                                                              \
            size_t base = (((size_t)(b * T_ + (tt)) * H_ + h) * 16) * 512;             \
            uint32_t* Ksb = shw + (buf) * BUF_W;                                       \
            uint32_t* Qsb = Ksb + KS_W;                                                \
            _Pragma("unroll")                                                          \
            for (int i = 0; i < 4; i++) {                                              \
                int f = tid + 512 * i;                                                 \
                int row = f >> 7, c = f & 127;                                         \
                cp16(&Ksb[row * 520 + 4 * c], g_Kp + base + (size_t)row * 512 + 4 * c);\
            }                                                                          \
            if (tid < 128) {                                                           \
                int row = tid >> 3, c = tid & 7;                                       \
                cp16(&Qsb[row * 40 + 4 * c],                                           \
                     g_Qp + base + (size_t)row * 512 + n0 + 4 * c);                    \
            }                                                                          \
        }

    SCORE_STAGE(0, 0);
    cp_commit();

    for (int t = 0; t < T_; t++) {
        int cur = t & 1;
        if (t + 1 < T_) {
            SCORE_STAGE(t + 1, cur ^ 1);
            cp_commit();
            cp_wait<1>();
        } else {
            cp_wait<0>();
        }
        __syncthreads();   // staging of t visible; rowsum[t-1] complete

        // consume previous iteration's probs (independent of this t's MMA)
        if (t > 0) {
            float (*pv)[4] = abuf[cur ^ 1];
            float inv0 = __fdividef(1.f, rowsum[(t - 1) * 32 + r_lo]);
            float inv1 = __fdividef(1.f, rowsum[(t - 1) * 32 + r_hi]);
            #pragma unroll
            for (int j = 0; j < 8; j++) {
                pacc[j][0] = fmaf(pv[j][0], inv0, pacc[j][0]);
                pacc[j][1] = fmaf(pv[j][1], inv0, pacc[j][1]);
                pacc[j][2] = fmaf(pv[j][2], inv1, pacc[j][2]);
                pacc[j][3] = fmaf(pv[j][3], inv1, pacc[j][3]);
            }
        }

        const uint32_t* Ksb = shw + cur * BUF_W;
        const uint32_t* Qsb = Ksb + KS_W;
        float (*acc)[4] = abuf[cur];
        #pragma unroll
        for (int j = 0; j < 8; j++)
            #pragma unroll
            for (int k = 0; k < 4; k++) acc[j][k] = 0.f;

        #pragma unroll
        for (int s = 0; s < 2; s++) {
            uint32_t a[4];
            a[0] = Qsb[(8 * s + lr) * 40 + r_lo];
            a[1] = Qsb[(8 * s + lr) * 40 + r_hi];
            a[2] = Qsb[(8 * s + lr + 4) * 40 + r_lo];
            a[3] = Qsb[(8 * s + lr + 4) * 40 + r_hi];
            #pragma unroll
            for (int j = 0; j < 8; j++) {
                int nc = 64 * colgrp + 8 * j + lq;
                uint32_t b0 = Ksb[(8 * s + lr) * 520 + nc];
                uint32_t b1 = Ksb[(8 * s + lr + 4) * 520 + nc];
                mma_bf16(acc[j], a, b0, b1);
            }
        }

        float s0 = 0.f, s1 = 0.f;
        #pragma unroll
        for (int j = 0; j < 8; j++) {
            acc[j][0] = ex2f(acc[j][0]);
            acc[j][1] = ex2f(acc[j][1]);
            acc[j][2] = ex2f(acc[j][2]);
            acc[j][3] = ex2f(acc[j][3]);
            s0 += acc[j][0] + acc[j][1];
            s1 += acc[j][2] + acc[j][3];
        }
        s0 += __shfl_xor_sync(0xffffffffu, s0, 1);
        s0 += __shfl_xor_sync(0xffffffffu, s0, 2);
        s1 += __shfl_xor_sync(0xffffffffu, s1, 1);
        s1 += __shfl_xor_sync(0xffffffffu, s1, 2);
        if (lr == 0) {
            atomicAdd(&rowsum[t * 32 + r_lo], s0);
            atomicAdd(&rowsum[t * 32 + r_hi], s1);
        }
        // no second barrier: consumption of rowsum[t] deferred to t+1
    }
    #undef SCORE_STAGE

    // drain last iteration
    __syncthreads();
    {
        float (*pv)[4] = abuf[(T_ - 1) & 1];
        float inv0 = __fdividef(1.f, rowsum[(T_ - 1) * 32 + r_lo]);
        float inv1 = __fdividef(1.f, rowsum[(T_ - 1) * 32 + r_hi]);
        #pragma unroll
        for (int j = 0; j < 8; j++) {
            pacc[j][0] = fmaf(pv[j][0], inv0, pacc[j][0]);
            pacc[j][1] = fmaf(pv[j][1], inv0, pacc[j][1]);
            pacc[j][2] = fmaf(pv[j][2], inv1, pacc[j][2]);
            pacc[j][3] = fmaf(pv[j][3], inv1, pacc[j][3]);
        }
    }

    size_t row0 = ((size_t)b * N_ + n0 + r_lo) * N_;
    size_t row1 = ((size_t)b * N_ + n0 + r_hi) * N_;
    #pragma unroll
    for (int j = 0; j < 8; j++) {
        int c = 64 * colgrp + 8 * j + 2 * lr;
        atomicAdd(&g_acc[row0 + c],     pacc[j][0]);
        atomicAdd(&g_acc[row0 + c + 1], pacc[j][1]);
        atomicAdd(&g_acc[row1 + c],     pacc[j][2]);
        atomicAdd(&g_acc[row1 + c + 1], pacc[j][3]);
    }
}

// ---------------- symmetrize + fuse + ex2 + tf32 round + row sums ----------------
__global__ __launch_bounds__(256) void sym_kernel(const float* __restrict__ fw,
                                                  const float* __restrict__ fb) {
    __shared__ float Am[64 * 33];
    __shared__ float Sm[64 * 33];
    int i0 = blockIdx.x * 32, j0 = blockIdx.y * 64, b = blockIdx.z;
    int tid = threadIdx.x, lane = tid & 31;
    float w0 = fw[0] * L2E, w1 = fw[1] * L2E, bias = fb[0] * L2E;
    const float* accb = g_acc + (size_t)b * N_ * N_;
    float* fz = g_fused + (size_t)b * N_ * N_;

    #pragma unroll
    for (int k = 0; k < 2; k++) {
        int f = tid + 256 * k;
        int r = f >> 3;
        int c4 = (f & 7) << 2;
        float4 a = *reinterpret_cast<const float4*>(&accb[(size_t)(j0 + r) * N_ + i0 + c4]);
        Am[r * 33 + c4 + 0] = a.x; Am[r * 33 + c4 + 1] = a.y;
        Am[r * 33 + c4 + 2] = a.z; Am[r * 33 + c4 + 3] = a.w;
        float4 s = *reinterpret_cast<const float4*>(&g_stS[(size_t)(j0 + r) * N_ + i0 + c4]);
        Sm[r * 33 + c4 + 0] = s.x; Sm[r * 33 + c4 + 1] = s.y;
        Sm[r * 33 + c4 + 2] = s.z; Sm[r * 33 + c4 + 3] = s.w;
    }
    __syncthreads();
    #pragma unroll
    for (int k = 0; k < 2; k++) {
        int r = k * 16 + (tid >> 4);
        int c4 = (tid & 15) << 2;
        float4 a = *reinterpret_cast<const float4*>(&accb[(size_t)(i0 + r) * N_ + j0 + c4]);
        float4 s = *reinterpret_cast<const float4*>(&g_stS[(size_t)(i0 + r) * N_ + j0 + c4]);
        float4 o;
        float an, sv;
        an = (a.x + Am[(c4 + 0) * 33 + r]) * (0.5f / 64.0f);
        sv = (s.x + Sm[(c4 + 0) * 33 + r]) * 0.5f;
        o.x = __uint_as_float(f2tf(ex2f(fmaf(w0, an, fmaf(w1, sv, bias)))));
        an = (a.y + Am[(c4 + 1) * 33 + r]) * (0.5f / 64.0f);
        sv = (s.y + Sm[(c4 + 1) * 33 + r]) * 0.5f;
        o.y = __uint_as_float(f2tf(ex2f(fmaf(w0, an, fmaf(w1, sv, bias)))));
        an = (a.z + Am[(c4 + 2) * 33 + r]) * (0.5f / 64.0f);
        sv = (s.z + Sm[(c4 + 2) * 33 + r]) * 0.5f;
        o.z = __uint_as_float(f2tf(ex2f(fmaf(w0, an, fmaf(w1, sv, bias)))));
        an = (a.w + Am[(c4 + 3) * 33 + r]) * (0.5f / 64.0f);
        sv = (s.w + Sm[(c4 + 3) * 33 + r]) * 0.5f;
        o.w = __uint_as_float(f2tf(ex2f(fmaf(w0, an, fmaf(w1, sv, bias)))));
        *reinterpret_cast<float4*>(&fz[(size_t)(i0 + r) * N_ + j0 + c4]) = o;
        float p = o.x + o.y + o.z + o.w;
        p += __shfl_xor_sync(0xffffffffu, p, 1);
        p += __shfl_xor_sync(0xffffffffu, p, 2);
        p += __shfl_xor_sync(0xffffffffu, p, 4);
        p += __shfl_xor_sync(0xffffffffu, p, 8);
        if ((lane & 15) == 0)
            atomicAdd(&g_S[(size_t)b * N_ + i0 + r], p);
    }
}

// ---------------- aggregation: pure LDS+MMA mainloop, epilogue normalize+transpose ----
__global__ __launch_bounds__(256, 2) void agg_kernel(float* __restrict__ out) {
    extern __shared__ float sh[];
    int n0 = blockIdx.x * 128, ct0 = blockIdx.y * 128, b = blockIdx.z;
    int tid = threadIdx.x, w = tid >> 5, lane = tid & 31;
    int wc = w & 1, wr = w >> 1;
    int lq = lane >> 2, lr = lane & 3;
    const float* xb = g_x2 + (size_t)b * C_ * T_ * N_;
    const float* fb = g_fused + (size_t)b * N_ * N_;

    float acc[2][8][4];
    #pragma unroll
    for (int m = 0; m < 2; m++)
        #pragma unroll
        for (int j = 0; j < 8; j++)
            #pragma unroll
            for (int k = 0; k < 4; k++) acc[m][j][k] = 0.f;

    #define AGG_STAGE(buf, kk)                                                      \
        {                                                                           \
            float* Xs = sh + (buf) * 9216;                                          \
            float* Fs = Xs + 4608;                                                  \
            _Pragma("unroll")                                                       \
            for (int i = 0; i < 4; i++) {                                           \
                int f = tid + 256 * i;                                              \
                int r = f >> 3, k4 = (f & 7) << 2;                                  \
                cp16(&Xs[r * 36 + k4], xb + (size_t)(ct0 + r) * N_ + (kk) + k4);    \
            }                                                                       \
            _Pragma("unroll")                                                       \
            for (int i = 0; i < 4; i++) {                                           \
                int f = tid + 256 * i;                                              \
                int r = f >> 3, k4 = (f & 7) << 2;                                  \
                cp16(&Fs[r * 36 + k4], fb + (size_t)(n0 + r) * N_ + (kk) + k4);     \
            }                                                                       \
        }

    AGG_STAGE(0, 0);
    cp_commit();

    for (int c = 0; c < 16; c++) {
        if (c < 15) {
            AGG_STAGE((c + 1) & 1, (c + 1) * 32);
            cp_commit();
            cp_wait<1>();
        } else {
            cp_wait<0>();
        }
        __syncthreads();
        const uint32_t* Xs = reinterpret_cast<const uint32_t*>(sh + (c & 1) * 9216);
        const uint32_t* Fs = Xs + 4608;

        #pragma unroll
        for (int s = 0; s < 4; s++) {
            uint32_t a[2][4];
            #pragma unroll
            for (int m = 0; m < 2; m++) {
                int r0 = 32 * wr + 16 * m + lq;
                a[m][0] = Xs[r0 * 36 + 8 * s + lr];
                a[m][1] = Xs[(r0 + 8) * 36 + 8 * s + lr];
                a[m][2] = Xs[r0 * 36 + 8 * s + lr + 4];
                a[m][3] = Xs[(r0 + 8) * 36 + 8 * s + lr + 4];
            }
            #pragma unroll
            for (int j = 0; j < 8; j++) {
                int n = 64 * wc + 8 * j + lq;
                uint32_t b0 = Fs[n * 36 + 8 * s + lr];
                uint32_t b1 = Fs[n * 36 + 8 * s + lr + 4];
                mma_tf32(acc[0][j], a[0], b0, b1);
                mma_tf32(acc[1][j], a[1], b0, b1);
            }
        }
        __syncthreads();
    }
    #undef AGG_STAGE

    {
        const float* Sp = g_S + (size_t)b * N_ + n0;
        #pragma unroll
        for (int j = 0; j < 8; j++) {
            int cc = 64 * wc + 8 * j + 2 * lr;
            float2 Sv = *reinterpret_cast<const float2*>(&Sp[cc]);
            float iv0 = __fdividef(1.f, Sv.x);
            float iv1 = __fdividef(1.f, Sv.y);
            #pragma unroll
            for (int m = 0; m < 2; m++) {
                acc[m][j][0] *= iv0; acc[m][j][1] *= iv1;
                acc[m][j][2] *= iv0; acc[m][j][3] *= iv1;
            }
        }
    }

    float* Ys = sh;
    #pragma unroll
    for (int m = 0; m < 2; m++) {
        int r0 = 32 * wr + 16 * m + lq;
        #pragma unroll
        for (int j = 0; j < 8; j++) {
            int cc = 64 * wc + 8 * j + 2 * lr;
            *reinterpret_cast<float2*>(&Ys[r0 * 130 + cc]) =
                make_float2(acc[m][j][0], acc[m][j][1]);
            *reinterpret_cast<float2*>(&Ys[(r0 + 8) * 130 + cc]) =
                make_float2(acc[m][j][2], acc[m][j][3]);
        }
    }
    __syncthreads();
    int c0 = blockIdx.y * 8;
    float* ob = out + (((size_t)b * C_ + c0) * N_ + n0) * T_;
    #pragma unroll
    for (int cl = 0; cl < 8; cl++) {
        #pragma unroll
        for (int p = 0; p < 2; p++) {
            int e4 = tid + 256 * p;
            int nn = e4 >> 2;
            int t0 = (e4 & 3) << 2;
            float4 v;
            v.x = Ys[(cl * 16 + t0 + 0) * 130 + nn];
            v.y = Ys[(cl * 16 + t0 + 1) * 130 + nn];
            v.z = Ys[(cl * 16 + t0 + 2) * 130 + nn];
            v.w = Ys[(cl * 16 + t0 + 3) * 130 + nn];
            *reinterpret_cast<float4*>(&ob[(size_t)cl * (N_ * T_) + nn * 16 + t0]) = v;
        }
    }
}

// ---------------- launcher ----------------
extern "C" void kernel_launch(void* const* d_in, const int* in_sizes, int n_in,
                              void* d_out, int out_size) {
    (void)in_sizes; (void)n_in; (void)out_size;
    const float* x    = (const float*)d_in[0];
    const float* Wq   = (const float*)d_in[1];
    const float* Wk   = (const float*)d_in[2];
    const float* st   = (const float*)d_in[3];
    const float* fw   = (const float*)d_in[4];
    const float* fbp  = (const float*)d_in[5];
    float* out = (float*)d_out;

    const int prep_smem  = 2 * 8208 * 4;                  // 65664
    const int proj_smem  = 22528 * 4;                     // 90112
    const int score_smem = (2 * 8960 + 512) * 4;          // 73728
    const int agg_smem   = 18432 * 4;                     // 73728
    cudaFuncSetAttribute(prep_kernel,  cudaFuncAttributeMaxDynamicSharedMemorySize, prep_smem);
    cudaFuncSetAttribute(proj_kernel,  cudaFuncAttributeMaxDynamicSharedMemorySize, proj_smem);
    cudaFuncSetAttribute(score_kernel, cudaFuncAttributeMaxDynamicSharedMemorySize, score_smem);
    cudaFuncSetAttribute(agg_kernel,   cudaFuncAttributeMaxDynamicSharedMemorySize, agg_smem);

    dummy_kernel<<<1, 32>>>();
    prep_kernel<<<1032, 256, prep_smem>>>(x, st, Wq, Wk);
    proj_kernel<<<dim3(4, B_ * T_), 256, proj_smem>>>();
    score_kernel<<<dim3(16, H_, B_), 512, score_smem>>>();
    sym_kernel<<<dim3(16, 8, B_), 256>>>(fw, fbp);
    agg_kernel<<<dim3(4, 16, B_), 256, agg_smem>>>(out);
}

// round 16
// speedup vs baseline: 1.1719x; 1.1719x over previous
#include <cuda_runtime.h>
#include <math.h>
#include <stdint.h>

#define B_ 4
#define C_ 128
#define N_ 512
#define T_ 16
#define H_ 4
#define DK_ 32
#define RSCALE 0.17677669529663687f   /* 1/sqrt(32) */
#define QSCALE 0.2550267247806026f    /* RSCALE * log2(e) */
#define L2E    1.4426950408889634f

// ---------------- PTX helpers ----------------
__device__ __forceinline__ void mma_tf32(float* d, const uint32_t* a, uint32_t b0, uint32_t b1) {
    asm("mma.sync.aligned.m16n8k8.row.col.f32.tf32.tf32.f32 "
        "{%0,%1,%2,%3}, {%4,%5,%6,%7}, {%8,%9}, {%0,%1,%2,%3};"
        : "+f"(d[0]), "+f"(d[1]), "+f"(d[2]), "+f"(d[3])
        : "r"(a[0]), "r"(a[1]), "r"(a[2]), "r"(a[3]), "r"(b0), "r"(b1));
}

__device__ __forceinline__ void mma_bf16(float* d, const uint32_t* a, uint32_t b0, uint32_t b1) {
    asm("mma.sync.aligned.m16n8k16.row.col.f32.bf16.bf16.f32 "
        "{%0,%1,%2,%3}, {%4,%5,%6,%7}, {%8,%9}, {%0,%1,%2,%3};"
        : "+f"(d[0]), "+f"(d[1]), "+f"(d[2]), "+f"(d[3])
        : "r"(a[0]), "r"(a[1]), "r"(a[2]), "r"(a[3]), "r"(b0), "r"(b1));
}

// round-to-nearest fp32 -> tf32 (fp32 bits, low 13 mantissa bits zero)
__device__ __forceinline__ uint32_t f2tf(float f) {
    uint32_t r;
    asm("cvt.rna.tf32.f32 %0, %1;" : "=r"(r) : "f"(f));
    return r;
}

// pack two fp32 -> bf16x2 {lo, hi}
__device__ __forceinline__ uint32_t bf2(float hi, float lo) {
    uint32_t r;
    asm("cvt.rn.bf16x2.f32 %0, %1, %2;" : "=r"(r) : "f"(hi), "f"(lo));
    return r;
}

__device__ __forceinline__ float ex2f(float x) {
    float r;
    asm("ex2.approx.f32 %0, %1;" : "=f"(r) : "f"(x));
    return r;
}

__device__ __forceinline__ void cp16(void* dst, const void* src) {
    uint32_t s = (uint32_t)__cvta_generic_to_shared(dst);
    asm volatile("cp.async.cg.shared.global [%0], [%1], 16;" :: "r"(s), "l"(src));
}
__device__ __forceinline__ void cp_commit() {
    asm volatile("cp.async.commit_group;" ::: "memory");
}
template <int NN> __device__ __forceinline__ void cp_wait() {
    asm volatile("cp.async.wait_group %0;" :: "n"(NN) : "memory");
}

// ---------------- scratch ----------------
__device__ float g_x2[B_*C_*T_*N_];            // x2[b][c][t][n], PRE-ROUNDED to tf32 grid
__device__ uint32_t g_x2b[B_*T_*64*512];       // bf16x2: [b][t][c2][n]
__device__ uint32_t g_Wqp[128*64];             // bf16x2 packed Wq[o][c2]
__device__ uint32_t g_Wkp[128*64];
__device__ uint32_t g_Qp[B_*T_*H_*16*512];     // bf16x2 QSCALE*Q pairs along d
__device__ uint32_t g_Kp[B_*T_*H_*16*512];
__device__ float g_acc[B_*N_*N_];              // sum over (t,h) of softmax probs
__device__ float g_stS[N_*N_];
__device__ float g_fused[B_*N_*N_];            // E = exp(logits), tf32-rounded, unnormalized
__device__ float g_S[B_*N_];                   // row sums of rounded E

// ---------------- small helpers ----------------
__device__ __forceinline__ float blk_reduce_max(float v, float* red, int tid) {
    #pragma unroll
    for (int off = 16; off > 0; off >>= 1)
        v = fmaxf(v, __shfl_xor_sync(0xffffffffu, v, off));
    if ((tid & 31) == 0) red[tid >> 5] = v;
    __syncthreads();
    if (tid == 0) {
        float m = red[0];
        #pragma unroll
        for (int k = 1; k < 8; k++) m = fmaxf(m, red[k]);
        red[0] = m;
    }
    __syncthreads();
    float r = red[0];
    __syncthreads();
    return r;
}

__device__ __forceinline__ float blk_reduce_sum(float v, float* red, int tid) {
    #pragma unroll
    for (int off = 16; off > 0; off >>= 1)
        v += __shfl_xor_sync(0xffffffffu, v, off);
    if ((tid & 31) == 0) red[tid >> 5] = v;
    __syncthreads();
    if (tid == 0) {
        float m = red[0];
        #pragma unroll
        for (int k = 1; k < 8; k++) m += red[k];
        red[0] = m;
    }
    __syncthreads();
    float r = red[0];
    __syncthreads();
    return r;
}

// ---------------- dummy (keeps score_kernel at ncu's capture slot) ----------------
__global__ void dummy_kernel() {}

// ---------------- prep ----------------
__global__ __launch_bounds__(256) void prep_kernel(const float* __restrict__ x,
                                                   const float* __restrict__ st,
                                                   const float* __restrict__ Wq,
                                                   const float* __restrict__ Wk) {
    extern __shared__ float dsh[];
    __shared__ float red[8];
    int bk = blockIdx.x, tid = threadIdx.x;
    if (bk < 256) {
        float* s0 = dsh;
        float* s1 = dsh + 8208;
        int bc0 = 2 * bk, bc1 = bc0 + 1;
        const float* src0 = x + (size_t)bc0 * (N_ * T_);
        const float* src1 = x + (size_t)bc1 * (N_ * T_);
        for (int i = tid; i < N_ * T_; i += 256) {
            int n = i >> 4, t = i & 15;
            s0[t * (N_ + 1) + n] = src0[i];
            s1[t * (N_ + 1) + n] = src1[i];
        }
        __syncthreads();
        float* dst0 = g_x2 + (size_t)bc0 * (T_ * N_);
        float* dst1 = g_x2 + (size_t)bc1 * (T_ * N_);
        int b = bc0 >> 7, c2 = (bc0 & 127) >> 1;
        for (int o = tid; o < N_ * T_; o += 256) {
            int t = o >> 9, n = o & 511;
            float v0 = s0[t * (N_ + 1) + n];
            float v1 = s1[t * (N_ + 1) + n];
            dst0[o] = __uint_as_float(f2tf(v0));
            dst1[o] = __uint_as_float(f2tf(v1));
            g_x2b[((size_t)(b * T_ + t) * 64 + c2) * 512 + n] = bf2(v1, v0);
        }
    } else if (bk < 768) {
        int i = bk - 256;
        float v0 = st[(size_t)i * N_ + tid];
        float v1 = st[(size_t)i * N_ + tid + 256];
        float m = blk_reduce_max(fmaxf(v0, v1), red, tid);
        float e0 = __expf(v0 - m), e1 = __expf(v1 - m);
        float ss = blk_reduce_sum(e0 + e1, red, tid);
        float inv = __fdividef(1.f, ss);
        g_stS[(size_t)i * N_ + tid] = e0 * inv;
        g_stS[(size_t)i * N_ + tid + 256] = e1 * inv;
    } else if (bk < 1024) {
        int zb = bk - 768;
        float4 z = make_float4(0.f, 0.f, 0.f, 0.f);
        float4* a4 = reinterpret_cast<float4*>(g_acc);
        #pragma unroll
        for (int k = 0; k < 4; k++)
            a4[(size_t)zb * 1024 + k * 256 + tid] = z;
        if (zb < 2)
            reinterpret_cast<float4*>(g_S)[zb * 256 + tid] = z;
    } else {
        int idx = (bk - 1024) * 1024 + tid * 4;
        #pragma unroll
        for (int u = 0; u < 4; u++) {
            int f = idx + u;
            int o = f >> 6, c2 = f & 63;
            float2 wv = *reinterpret_cast<const float2*>(&Wq[o * 128 + 2 * c2]);
            g_Wqp[f] = bf2(wv.y, wv.x);
            float2 kv = *reinterpret_cast<const float2*>(&Wk[o * 128 + 2 * c2]);
            g_Wkp[f] = bf2(kv.y, kv.x);
        }
    }
}

// ---------------- projection via bf16 m16n8k16 (merged Q+K, pre-packed W) --------
__global__ __launch_bounds__(256, 2) void proj_kernel() {
    extern __shared__ uint32_t shw[];
    uint32_t* Wqp = shw;
    uint32_t* Wkp = shw + 8704;
    uint32_t* Xb0 = shw + 17408;
    uint32_t* Xb1 = shw + 19968;
    int n0 = blockIdx.x * 128;
    int bt = blockIdx.y;
    int b = bt >> 4, t = bt & 15;
    int tid = threadIdx.x, w = tid >> 5, lane = tid & 31;
    int lq = lane >> 2, lr = lane & 3;
    int o_lo = 16 * w + lq, o_hi = o_lo + 8;

    const uint32_t* xsrc = g_x2b + ((size_t)(b * T_ + t) * 64) * 512 + n0;

    #define PROJ_STAGE(X, ch)                                                          \
        {                                                                              \
            _Pragma("unroll")                                                          \
            for (int i = 0; i < 2; i++) {                                              \
                int f = tid + 256 * i;                                                 \
                int c2 = f >> 3, g = f & 7;                                            \
                cp16(&(X)[c2 * 40 + 4 * g], xsrc + (size_t)c2 * 512 + (ch) * 32 + 4 * g); \
            }                                                                          \
        }

    #pragma unroll
    for (int i = 0; i < 8; i++) {
        int f = tid + 256 * i;
        int o = f >> 4, g = f & 15;
        cp16(&Wqp[o * 68 + 4 * g], &g_Wqp[o * 64 + 4 * g]);
        cp16(&Wkp[o * 68 + 4 * g], &g_Wkp[o * 64 + 4 * g]);
    }
    cp_commit();
    PROJ_STAGE(Xb0, 0);
    cp_commit();

    cp_wait<1>();
    __syncthreads();

    uint32_t aq[8][4];
    #pragma unroll
    for (int s = 0; s < 8; s++) {
        aq[s][0] = Wqp[o_lo * 68 + 8 * s + lr];
        aq[s][1] = Wqp[o_hi * 68 + 8 * s + lr];
        aq[s][2] = Wqp[o_lo * 68 + 8 * s + lr + 4];
        aq[s][3] = Wqp[o_hi * 68 + 8 * s + lr + 4];
    }

    int h = w >> 1;
    bool qside = ((lane & 4) == 0);
    int o_loc = (16 * w + lq) & 31;
    int d2 = (qside ? o_loc : (o_loc - 1)) >> 1;
    size_t kb = (((size_t)(b * T_ + t) * H_ + h) * 16) * 512;

    for (int ch = 0; ch < 4; ch++) {
        uint32_t* Xn = (ch & 1) ? Xb0 : Xb1;
        if (ch < 3) {
            PROJ_STAGE(Xn, ch + 1);
            cp_commit();
            cp_wait<1>();
        } else {
            cp_wait<0>();
        }
        __syncthreads();
        const uint32_t* X = (ch & 1) ? Xb1 : Xb0;

        float accq[4][4], acck[4][4];
        #pragma unroll
        for (int j = 0; j < 4; j++)
            #pragma unroll
            for (int k = 0; k < 4; k++) { accq[j][k] = 0.f; acck[j][k] = 0.f; }

        #pragma unroll
        for (int s = 0; s < 8; s++) {
            uint32_t ak[4];
            ak[0] = Wkp[o_lo * 68 + 8 * s + lr];
            ak[1] = Wkp[o_hi * 68 + 8 * s + lr];
            ak[2] = Wkp[o_lo * 68 + 8 * s + lr + 4];
            ak[3] = Wkp[o_hi * 68 + 8 * s + lr + 4];
            #pragma unroll
            for (int j = 0; j < 4; j++) {
                uint32_t b0 = X[(8 * s + lr) * 40 + 8 * j + lq];
                uint32_t b1 = X[(8 * s + lr + 4) * 40 + 8 * j + lq];
                mma_bf16(accq[j], aq[s], b0, b1);
                mma_bf16(acck[j], ak, b0, b1);
            }
        }

        #pragma unroll
        for (int j = 0; j < 4; j++)
            #pragma unroll
            for (int k = 0; k < 4; k++) accq[j][k] *= QSCALE;

        #pragma unroll
        for (int j = 0; j < 4; j++) {
            float q0 = __shfl_xor_sync(0xffffffffu, accq[j][0], 4);
            float q1 = __shfl_xor_sync(0xffffffffu, accq[j][1], 4);
            float q2 = __shfl_xor_sync(0xffffffffu, accq[j][2], 4);
            float q3 = __shfl_xor_sync(0xffffffffu, accq[j][3], 4);
            float k0 = __shfl_xor_sync(0xffffffffu, acck[j][0], 4);
            float k1 = __shfl_xor_sync(0xffffffffu, acck[j][1], 4);
            float k2 = __shfl_xor_sync(0xffffffffu, acck[j][2], 4);
            float k3 = __shfl_xor_sync(0xffffffffu, acck[j][3], 4);
            int n = n0 + ch * 32 + 8 * j + 2 * lr;
            uint2 lo2, hi2;
            uint32_t* dst;
            if (qside) {
                dst = g_Qp;
                lo2.x = bf2(q0, accq[j][0]); lo2.y = bf2(q1, accq[j][1]);
                hi2.x = bf2(q2, accq[j][2]); hi2.y = bf2(q3, accq[j][3]);
            } else {
                dst = g_Kp;
                lo2.x = bf2(acck[j][0], k0); lo2.y = bf2(acck[j][1], k1);
                hi2.x = bf2(acck[j][2], k2); hi2.y = bf2(acck[j][3], k3);
            }
            *reinterpret_cast<uint2*>(&dst[kb + (size_t)d2 * 512 + n]) = lo2;
            *reinterpret_cast<uint2*>(&dst[kb + (size_t)(d2 + 4) * 512 + n]) = hi2;
        }
        __syncthreads();
    }
    #undef PROJ_STAGE
}

// ---------------- scores: 16 q-rows/block, 256 threads (8 colgrp warps), 3 CTAs/SM ----
// Same two-barrier structure as the proven R13 kernel; smaller blocks let 3
// independent CTAs per SM hide barrier/chain stalls.
__global__ __launch_bounds__(256, 3) void score_kernel() {
    extern __shared__ uint32_t shw[];
    const int KS_W = 16 * 520;    // 8320
    const int QS_W = 16 * 20;     // 320
    const int BUF_W = KS_W + QS_W; // 8640
    float* rowsum = reinterpret_cast<float*>(shw + 2 * BUF_W);   // [16 t][16 rows]
    int nt = blockIdx.x, h = blockIdx.y, b = blockIdx.z;
    int n0 = nt * 16;
    int tid = threadIdx.x, w = tid >> 5, lane = tid & 31;
    int colgrp = w;                       // 0..7, 64 cols each
    int lq = lane >> 2, lr = lane & 3;
    int r_lo = lq, r_hi = lq + 8;

    rowsum[tid] = 0.f;   // 256 = 16*16 exactly

    float pacc[8][4];
    #pragma unroll
    for (int j = 0; j < 8; j++)
        #pragma unroll
        for (int k = 0; k < 4; k++) pacc[j][k] = 0.f;

    #define SCORE_STAGE(tt, buf)                                                       \
        {                                                                              \
            size_t base = (((size_t)(b * T_ + (tt)) * H_ + h) * 16) * 512;             \
            uint32_t* Ksb = shw + (buf) * BUF_W;                                       \
            uint32_t* Qsb = Ksb + KS_W;                                                \
            _Pragma("unroll")                                                          \
            for (int i = 0; i < 8; i++) {                                              \
                int f = tid + 256 * i;                                                 \
                int row = f >> 7, c = f & 127;                                         \
                cp16(&Ksb[row * 520 + 4 * c], g_Kp + base + (size_t)row * 512 + 4 * c);\
            }                                                                          \
            if (tid < 64) {                                                            \
                int row = tid >> 2, c = tid & 3;                                       \
                cp16(&Qsb[row * 20 + 4 * c],                                           \
                     g_Qp + base + (size_t)row * 512 + n0 + 4 * c);                    \
            }                                                                          \
        }

    SCORE_STAGE(0, 0);
    cp_commit();

    for (int t = 0; t < T_; t++) {
        int cur = t & 1;
        if (t + 1 < T_) {
            SCORE_STAGE(t + 1, cur ^ 1);
            cp_commit();
            cp_wait<1>();
        } else {
            cp_wait<0>();
        }
        __syncthreads();
        const uint32_t* Ksb = shw + cur * BUF_W;
        const uint32_t* Qsb = Ksb + KS_W;

        float acc[8][4];
        #pragma unroll
        for (int j = 0; j < 8; j++)
            #pragma unroll
            for (int k = 0; k < 4; k++) acc[j][k] = 0.f;

        #pragma unroll
        for (int s = 0; s < 2; s++) {
            uint32_t a[4];
            a[0] = Qsb[(8 * s + lr) * 20 + r_lo];
            a[1] = Qsb[(8 * s + lr) * 20 + r_hi];
            a[2] = Qsb[(8 * s + lr + 4) * 20 + r_lo];
            a[3] = Qsb[(8 * s + lr + 4) * 20 + r_hi];
            #pragma unroll
            for (int j = 0; j < 8; j++) {
                int nc = 64 * colgrp + 8 * j + lq;
                uint32_t b0 = Ksb[(8 * s + lr) * 520 + nc];
                uint32_t b1 = Ksb[(8 * s + lr + 4) * 520 + nc];
                mma_bf16(acc[j], a, b0, b1);
            }
        }

        float s0 = 0.f, s1 = 0.f;
        #pragma unroll
        for (int j = 0; j < 8; j++) {
            acc[j][0] = ex2f(acc[j][0]);
            acc[j][1] = ex2f(acc[j][1]);
            acc[j][2] = ex2f(acc[j][2]);
            acc[j][3] = ex2f(acc[j][3]);
            s0 += acc[j][0] + acc[j][1];
            s1 += acc[j][2] + acc[j][3];
        }
        s0 += __shfl_xor_sync(0xffffffffu, s0, 1);
        s0 += __shfl_xor_sync(0xffffffffu, s0, 2);
        s1 += __shfl_xor_sync(0xffffffffu, s1, 1);
        s1 += __shfl_xor_sync(0xffffffffu, s1, 2);
        if (lr == 0) {
            atomicAdd(&rowsum[t * 16 + r_lo], s0);
            atomicAdd(&rowsum[t * 16 + r_hi], s1);
        }
        __syncthreads();   // rowsum complete; all MMA reads of cur done -> safe to restage
        float inv0 = __fdividef(1.f, rowsum[t * 16 + r_lo]);
        float inv1 = __fdividef(1.f, rowsum[t * 16 + r_hi]);
        #pragma unroll
        for (int j = 0; j < 8; j++) {
            pacc[j][0] = fmaf(acc[j][0], inv0, pacc[j][0]);
            pacc[j][1] = fmaf(acc[j][1], inv0, pacc[j][1]);
            pacc[j][2] = fmaf(acc[j][2], inv1, pacc[j][2]);
            pacc[j][3] = fmaf(acc[j][3], inv1, pacc[j][3]);
        }
    }
    #undef SCORE_STAGE

    size_t row0 = ((size_t)b * N_ + n0 + r_lo) * N_;
    size_t row1 = ((size_t)b * N_ + n0 + r_hi) * N_;
    #pragma unroll
    for (int j = 0; j < 8; j++) {
        int c = 64 * colgrp + 8 * j + 2 * lr;
        atomicAdd(&g_acc[row0 + c],     pacc[j][0]);
        atomicAdd(&g_acc[row0 + c + 1], pacc[j][1]);
        atomicAdd(&g_acc[row1 + c],     pacc[j][2]);
        atomicAdd(&g_acc[row1 + c + 1], pacc[j][3]);
    }
}

// ---------------- symmetrize + fuse + ex2 + tf32 round + row sums ----------------
__global__ __launch_bounds__(256) void sym_kernel(const float* __restrict__ fw,
                                                  const float* __restrict__ fb) {
    __shared__ float Am[64 * 33];
    __shared__ float Sm[64 * 33];
    int i0 = blockIdx.x * 32, j0 = blockIdx.y * 64, b = blockIdx.z;
    int tid = threadIdx.x, lane = tid & 31;
    float w0 = fw[0] * L2E, w1 = fw[1] * L2E, bias = fb[0] * L2E;
    const float* accb = g_acc + (size_t)b * N_ * N_;
    float* fz = g_fused + (size_t)b * N_ * N_;

    #pragma unroll
    for (int k = 0; k < 2; k++) {
        int f = tid + 256 * k;
        int r = f >> 3;
        int c4 = (f & 7) << 2;
        float4 a = *reinterpret_cast<const float4*>(&accb[(size_t)(j0 + r) * N_ + i0 + c4]);
        Am[r * 33 + c4 + 0] = a.x; Am[r * 33 + c4 + 1] = a.y;
        Am[r * 33 + c4 + 2] = a.z; Am[r * 33 + c4 + 3] = a.w;
        float4 s = *reinterpret_cast<const float4*>(&g_stS[(size_t)(j0 + r) * N_ + i0 + c4]);
        Sm[r * 33 + c4 + 0] = s.x; Sm[r * 33 + c4 + 1] = s.y;
        Sm[r * 33 + c4 + 2] = s.z; Sm[r * 33 + c4 + 3] = s.w;
    }
    __syncthreads();
    #pragma unroll
    for (int k = 0; k < 2; k++) {
        int r = k * 16 + (tid >> 4);
        int c4 = (tid & 15) << 2;
        float4 a = *reinterpret_cast<const float4*>(&accb[(size_t)(i0 + r) * N_ + j0 + c4]);
        float4 s = *reinterpret_cast<const float4*>(&g_stS[(size_t)(i0 + r) * N_ + j0 + c4]);
        float4 o;
        float an, sv;
        an = (a.x + Am[(c4 + 0) * 33 + r]) * (0.5f / 64.0f);
        sv = (s.x + Sm[(c4 + 0) * 33 + r]) * 0.5f;
        o.x = __uint_as_float(f2tf(ex2f(fmaf(w0, an, fmaf(w1, sv, bias)))));
        an = (a.y + Am[(c4 + 1) * 33 + r]) * (0.5f / 64.0f);
        sv = (s.y + Sm[(c4 + 1) * 33 + r]) * 0.5f;
        o.y = __uint_as_float(f2tf(ex2f(fmaf(w0, an, fmaf(w1, sv, bias)))));
        an = (a.z + Am[(c4 + 2) * 33 + r]) * (0.5f / 64.0f);
        sv = (s.z + Sm[(c4 + 2) * 33 + r]) * 0.5f;
        o.z = __uint_as_float(f2tf(ex2f(fmaf(w0, an, fmaf(w1, sv, bias)))));
        an = (a.w + Am[(c4 + 3) * 33 + r]) * (0.5f / 64.0f);
        sv = (s.w + Sm[(c4 + 3) * 33 + r]) * 0.5f;
        o.w = __uint_as_float(f2tf(ex2f(fmaf(w0, an, fmaf(w1, sv, bias)))));
        *reinterpret_cast<float4*>(&fz[(size_t)(i0 + r) * N_ + j0 + c4]) = o;
        float p = o.x + o.y + o.z + o.w;
        p += __shfl_xor_sync(0xffffffffu, p, 1);
        p += __shfl_xor_sync(0xffffffffu, p, 2);
        p += __shfl_xor_sync(0xffffffffu, p, 4);
        p += __shfl_xor_sync(0xffffffffu, p, 8);
        if ((lane & 15) == 0)
            atomicAdd(&g_S[(size_t)b * N_ + i0 + r], p);
    }
}

// ---------------- aggregation: pure LDS+MMA mainloop, epilogue normalize+transpose ----
__global__ __launch_bounds__(256, 2) void agg_kernel(float* __restrict__ out) {
    extern __shared__ float sh[];
    int n0 = blockIdx.x * 128, ct0 = blockIdx.y * 128, b = blockIdx.z;
    int tid = threadIdx.x, w = tid >> 5, lane = tid & 31;
    int wc = w & 1, wr = w >> 1;
    int lq = lane >> 2, lr = lane & 3;
    const float* xb = g_x2 + (size_t)b * C_ * T_ * N_;
    const float* fb = g_fused + (size_t)b * N_ * N_;

    float acc[2][8][4];
    #pragma unroll
    for (int m = 0; m < 2; m++)
        #pragma unroll
        for (int j = 0; j < 8; j++)
            #pragma unroll
            for (int k = 0; k < 4; k++) acc[m][j][k] = 0.f;

    #define AGG_STAGE(buf, kk)                                                      \
        {                                                                           \
            float* Xs = sh + (buf) * 9216;                                          \
            float* Fs = Xs + 4608;                                                  \
            _Pragma("unroll")                                                       \
            for (int i = 0; i < 4; i++) {                                           \
                int f = tid + 256 * i;                                              \
                int r = f >> 3, k4 = (f & 7) << 2;                                  \
                cp16(&Xs[r * 36 + k4], xb + (size_t)(ct0 + r) * N_ + (kk) + k4);    \
            }                                                                       \
            _Pragma("unroll")                                                       \
            for (int i = 0; i < 4; i++) {                                           \
                int f = tid + 256 * i;                                              \
                int r = f >> 3, k4 = (f & 7) << 2;                                  \
                cp16(&Fs[r * 36 + k4], fb + (size_t)(n0 + r) * N_ + (kk) + k4);     \
            }                                                                       \
        }

    AGG_STAGE(0, 0);
    cp_commit();

    for (int c = 0; c < 16; c++) {
        if (c < 15) {
            AGG_STAGE((c + 1) & 1, (c + 1) * 32);
            cp_commit();
            cp_wait<1>();
        } else {
            cp_wait<0>();
        }
        __syncthreads();
        const uint32_t* Xs = reinterpret_cast<const uint32_t*>(sh + (c & 1) * 9216);
        const uint32_t* Fs = Xs + 4608;

        #pragma unroll
        for (int s = 0; s < 4; s++) {
            uint32_t a[2][4];
            #pragma unroll
            for (int m = 0; m < 2; m++) {
                int r0 = 32 * wr + 16 * m + lq;
                a[m][0] = Xs[r0 * 36 + 8 * s + lr];
                a[m][1] = Xs[(r0 + 8) * 36 + 8 * s + lr];
                a[m][2] = Xs[r0 * 36 + 8 * s + lr + 4];
                a[m][3] = Xs[(r0 + 8) * 36 + 8 * s + lr + 4];
            }
            #pragma unroll
            for (int j = 0; j < 8; j++) {
                int n = 64 * wc + 8 * j + lq;
                uint32_t b0 = Fs[n * 36 + 8 * s + lr];
                uint32_t b1 = Fs[n * 36 + 8 * s + lr + 4];
                mma_tf32(acc[0][j], a[0], b0, b1);
                mma_tf32(acc[1][j], a[1], b0, b1);
            }
        }
        __syncthreads();
    }
    #undef AGG_STAGE

    {
        const float* Sp = g_S + (size_t)b * N_ + n0;
        #pragma unroll
        for (int j = 0; j < 8; j++) {
            int cc = 64 * wc + 8 * j + 2 * lr;
            float2 Sv = *reinterpret_cast<const float2*>(&Sp[cc]);
            float iv0 = __fdividef(1.f, Sv.x);
            float iv1 = __fdividef(1.f, Sv.y);
            #pragma unroll
            for (int m = 0; m < 2; m++) {
                acc[m][j][0] *= iv0; acc[m][j][1] *= iv1;
                acc[m][j][2] *= iv0; acc[m][j][3] *= iv1;
            }
        }
    }

    float* Ys = sh;
    #pragma unroll
    for (int m = 0; m < 2; m++) {
        int r0 = 32 * wr + 16 * m + lq;
        #pragma unroll
        for (int j = 0; j < 8; j++) {
            int cc = 64 * wc + 8 * j + 2 * lr;
            *reinterpret_cast<float2*>(&Ys[r0 * 130 + cc]) =
                make_float2(acc[m][j][0], acc[m][j][1]);
            *reinterpret_cast<float2*>(&Ys[(r0 + 8) * 130 + cc]) =
                make_float2(acc[m][j][2], acc[m][j][3]);
        }
    }
    __syncthreads();
    int c0 = blockIdx.y * 8;
    float* ob = out + (((size_t)b * C_ + c0) * N_ + n0) * T_;
    #pragma unroll
    for (int cl = 0; cl < 8; cl++) {
        #pragma unroll
        for (int p = 0; p < 2; p++) {
            int e4 = tid + 256 * p;
            int nn = e4 >> 2;
            int t0 = (e4 & 3) << 2;
            float4 v;
            v.x = Ys[(cl * 16 + t0 + 0) * 130 + nn];
            v.y = Ys[(cl * 16 + t0 + 1) * 130 + nn];
            v.z = Ys[(cl * 16 + t0 + 2) * 130 + nn];
            v.w = Ys[(cl * 16 + t0 + 3) * 130 + nn];
            *reinterpret_cast<float4*>(&ob[(size_t)cl * (N_ * T_) + nn * 16 + t0]) = v;
        }
    }
}

// ---------------- launcher ----------------
extern "C" void kernel_launch(void* const* d_in, const int* in_sizes, int n_in,
                              void* d_out, int out_size) {
    (void)in_sizes; (void)n_in; (void)out_size;
    const float* x    = (const float*)d_in[0];
    const float* Wq   = (const float*)d_in[1];
    const float* Wk   = (const float*)d_in[2];
    const float* st   = (const float*)d_in[3];
    const float* fw   = (const float*)d_in[4];
    const float* fbp  = (const float*)d_in[5];
    float* out = (float*)d_out;

    const int prep_smem  = 2 * 8208 * 4;                  // 65664
    const int proj_smem  = 22528 * 4;                     // 90112
    const int score_smem = (2 * 8640 + 256) * 4;          // 70144
    const int agg_smem   = 18432 * 4;                     // 73728
    cudaFuncSetAttribute(prep_kernel,  cudaFuncAttributeMaxDynamicSharedMemorySize, prep_smem);
    cudaFuncSetAttribute(proj_kernel,  cudaFuncAttributeMaxDynamicSharedMemorySize, proj_smem);
    cudaFuncSetAttribute(score_kernel, cudaFuncAttributeMaxDynamicSharedMemorySize, score_smem);
    cudaFuncSetAttribute(agg_kernel,   cudaFuncAttributeMaxDynamicSharedMemorySize, agg_smem);

    dummy_kernel<<<1, 32>>>();
    prep_kernel<<<1032, 256, prep_smem>>>(x, st, Wq, Wk);
    proj_kernel<<<dim3(4, B_ * T_), 256, proj_smem>>>();
    score_kernel<<<dim3(32, H_, B_), 256, score_smem>>>();
    sym_kernel<<<dim3(16, 8, B_), 256>>>(fw, fbp);
    agg_kernel<<<dim3(4, 16, B_), 256, agg_smem>>>(out);
}